// round 7
// baseline (speedup 1.0000x reference)
#include <cuda_runtime.h>
#include <cuda_bf16.h>

#define TILE_CHUNKS 256          // float4 chunks per tile (= 1024 elems)
#define MAX_TILES  16384
__device__ float g_tile_sum[MAX_TILES];
__device__ int   g_work = 0;     // work-stealing cursor
__device__ int   g_done = 0;     // CTA completion counter

// ---------------------------------------------------------------------------
// Persistent work-stealing kernel. Grid == exactly-resident CTAs (one wave).
// Warps steal half-row tiles via an atomic cursor -> no wave quantization and
// no length-imbalance tail. Each tile's partial sum is computed with a FIXED
// lane mapping and accumulation order and stored at g_tile_sum[tileId], so
// the result is bitwise identical regardless of which warp stole the tile;
// the last CTA reduces tile IDs in fixed order -> fully deterministic.
//   loss = (1/B) * sum_row (1/L) * sum_{t<L} (pred - log(align))^2
// ---------------------------------------------------------------------------
template <int BLOCK>
__global__ void __launch_bounds__(BLOCK)
dploss_steal_kernel(const float* __restrict__ pred,
                    const float* __restrict__ align,
                    const int* __restrict__ lens,
                    float* __restrict__ out,
                    int C,            // float4 chunks per row (T/4)
                    int tilesPerRow,  // ceil(C / TILE_CHUNKS)
                    int nTiles,
                    int B) {
    const int lane = threadIdx.x & 31;

    while (true) {
        int t;
        if (lane == 0) t = atomicAdd(&g_work, 1);
        t = __shfl_sync(0xFFFFFFFFu, t, 0);
        if (t >= nTiles) break;

        const int row  = t / tilesPerRow;
        const int seg  = t - row * tilesPerRow;
        const int L    = __ldg(lens + row);
        const int start = seg * TILE_CHUNKS;
        const int nfull = L >> 2;                 // fully-valid chunks in row
        const int V     = (L + 3) >> 2;           // valid chunks incl. partial

        float s0 = 0.0f, s1 = 0.0f, s2 = 0.0f, s3 = 0.0f;

        if (start < V) {
            const size_t base = (size_t)row * (size_t)C;
            const float4* __restrict__ p4 = reinterpret_cast<const float4*>(pred) + base;
            const float4* __restrict__ a4 = reinterpret_cast<const float4*>(align) + base;

            const int full_end = min(start + TILE_CHUNKS, nfull);
            int c = start + lane;

            // Hot loop: 4 full chunks, 8 independent LDG.128 batched.
            for (; c + 96 < full_end; c += 128) {
                float4 pA = p4[c];
                float4 aA = a4[c];
                float4 pB = p4[c + 32];
                float4 aB = a4[c + 32];
                float4 pC = p4[c + 64];
                float4 aC = a4[c + 64];
                float4 pD = p4[c + 96];
                float4 aD = a4[c + 96];

                float d;
                d = pA.x - __logf(aA.x); s0 = fmaf(d, d, s0);
                d = pA.y - __logf(aA.y); s0 = fmaf(d, d, s0);
                d = pA.z - __logf(aA.z); s0 = fmaf(d, d, s0);
                d = pA.w - __logf(aA.w); s0 = fmaf(d, d, s0);
                d = pB.x - __logf(aB.x); s1 = fmaf(d, d, s1);
                d = pB.y - __logf(aB.y); s1 = fmaf(d, d, s1);
                d = pB.z - __logf(aB.z); s1 = fmaf(d, d, s1);
                d = pB.w - __logf(aB.w); s1 = fmaf(d, d, s1);
                d = pC.x - __logf(aC.x); s2 = fmaf(d, d, s2);
                d = pC.y - __logf(aC.y); s2 = fmaf(d, d, s2);
                d = pC.z - __logf(aC.z); s2 = fmaf(d, d, s2);
                d = pC.w - __logf(aC.w); s2 = fmaf(d, d, s2);
                d = pD.x - __logf(aD.x); s3 = fmaf(d, d, s3);
                d = pD.y - __logf(aD.y); s3 = fmaf(d, d, s3);
                d = pD.z - __logf(aD.z); s3 = fmaf(d, d, s3);
                d = pD.w - __logf(aD.w); s3 = fmaf(d, d, s3);
            }
            // Remaining full chunks.
            for (; c < full_end; c += 32) {
                float4 p = p4[c];
                float4 a = a4[c];
                float d;
                d = p.x - __logf(a.x); s0 = fmaf(d, d, s0);
                d = p.y - __logf(a.y); s1 = fmaf(d, d, s1);
                d = p.z - __logf(a.z); s2 = fmaf(d, d, s2);
                d = p.w - __logf(a.w); s3 = fmaf(d, d, s3);
            }
            // Partial tail chunk (1..3 valid elems) if it falls in this tile.
            // Safe read: L&3 != 0 implies L < T, so chunk nfull < C.
            if ((L & 3) && nfull >= start && nfull < start + TILE_CHUNKS &&
                lane == (nfull & 31)) {
                float4 p = p4[nfull];
                float4 a = a4[nfull];
                int rem = L & 3;
                float d;
                d = p.x - __logf(a.x); s0 = fmaf(d, d, s0);
                if (rem > 1) { d = p.y - __logf(a.y); s1 = fmaf(d, d, s1); }
                if (rem > 2) { d = p.z - __logf(a.z); s2 = fmaf(d, d, s2); }
            }
        }

        float s = (s0 + s1) + (s2 + s3);
        #pragma unroll
        for (int off = 16; off > 0; off >>= 1)
            s += __shfl_down_sync(0xFFFFFFFFu, s, off);
        if (lane == 0)
            g_tile_sum[t] = s * __frcp_rn((float)L);   // 0 for empty tiles
    }

    // Completion; last CTA reduces all tiles in fixed order, resets state.
    __syncthreads();
    __shared__ bool s_is_last;
    if (threadIdx.x == 0) {
        __threadfence();
        int old = atomicAdd(&g_done, 1);
        s_is_last = (old == (int)gridDim.x - 1);
    }
    __syncthreads();

    if (s_is_last) {
        float v = 0.0f;
        for (int i = threadIdx.x; i < nTiles; i += BLOCK)   // fixed order
            v += g_tile_sum[i];
        __shared__ float warp_sums[BLOCK / 32];
        #pragma unroll
        for (int off = 16; off > 0; off >>= 1)
            v += __shfl_down_sync(0xFFFFFFFFu, v, off);
        if ((threadIdx.x & 31) == 0)
            warp_sums[threadIdx.x >> 5] = v;
        __syncthreads();
        if (threadIdx.x == 0) {
            float tt = 0.0f;
            #pragma unroll
            for (int w = 0; w < BLOCK / 32; w++)
                tt += warp_sums[w];
            out[0] = tt / (float)B;
            g_work = 0;    // reset for next graph replay
            g_done = 0;
        }
    }
}

extern "C" void kernel_launch(void* const* d_in, const int* in_sizes, int n_in,
                              void* d_out, int out_size) {
    const float* pred  = (const float*)d_in[0];
    const float* align = (const float*)d_in[1];
    const int*   lens  = (const int*)d_in[2];
    float* out = (float*)d_out;

    const int B = in_sizes[2];
    const int T = in_sizes[0] / B;
    const int C = T >> 2;
    const int tilesPerRow = (C + TILE_CHUNKS - 1) / TILE_CHUNKS;
    int nTiles = B * tilesPerRow;
    if (nTiles > MAX_TILES) nTiles = MAX_TILES;   // (not hit for B=4096,T=2048)

    constexpr int BLOCK = 256;       // 8 warps/CTA
    const int grid = 148 * 4;        // exactly-resident persistent wave

    dploss_steal_kernel<BLOCK><<<grid, BLOCK>>>(pred, align, lens, out,
                                                C, tilesPerRow, nTiles, B);
}

// round 8
// speedup vs baseline: 1.5778x; 1.5778x over previous
#include <cuda_runtime.h>
#include <cuda_bf16.h>

#define MAX_B 8192
__device__ float g_row_mse[MAX_B];
__device__ int   g_done_ctr = 0;

// ---------------------------------------------------------------------------
// Warp-per-row, small CTAs, explicit reg budget.
//   BLOCK=128 (4 warps), grid=1024 -> 4096 warps == one warp per row.
//   __launch_bounds__(128, 7): reg cap 73/thread -> all 8 float4 load
//   destinations of the hot loop stay live (real MLP ~8), while 7 CTAs/SM
//   x 148 SMs = 1036 >= 1024 keeps the whole grid in ONE resident wave.
//   loss = (1/B) * sum_row (1/L) * sum_{t<L} (pred - log(align))^2
// Deterministic: per-row results statically owned; fixed-order final reduce.
// ---------------------------------------------------------------------------
template <int BLOCK>
__global__ void __launch_bounds__(BLOCK, 7)
dploss_warprow_kernel(const float* __restrict__ pred,
                      const float* __restrict__ align,
                      const int* __restrict__ lens,
                      float* __restrict__ out,
                      int C,   // float4 chunks per row (T/4)
                      int B) {
    const int lane = threadIdx.x & 31;
    const int warpsPerGrid = (gridDim.x * BLOCK) >> 5;
    const int warpId = (blockIdx.x * BLOCK + threadIdx.x) >> 5;

    for (int row = warpId; row < B; row += warpsPerGrid) {
        const int L = __ldg(lens + row);          // one lens load per row
        const int nfull = L >> 2;                 // fully-valid chunks
        const size_t base = (size_t)row * (size_t)C;
        const float4* __restrict__ p4 = reinterpret_cast<const float4*>(pred) + base;
        const float4* __restrict__ a4 = reinterpret_cast<const float4*>(align) + base;

        float s0 = 0.0f, s1 = 0.0f, s2 = 0.0f, s3 = 0.0f;

        int c = lane;
        // Hot loop: 4 full chunks/iteration, 8 independent LDG.128 all live.
        for (; c + 96 < nfull; c += 128) {
            float4 pA = p4[c];
            float4 aA = a4[c];
            float4 pB = p4[c + 32];
            float4 aB = a4[c + 32];
            float4 pC = p4[c + 64];
            float4 aC = a4[c + 64];
            float4 pD = p4[c + 96];
            float4 aD = a4[c + 96];

            float d;
            d = pA.x - __logf(aA.x); s0 = fmaf(d, d, s0);
            d = pA.y - __logf(aA.y); s0 = fmaf(d, d, s0);
            d = pA.z - __logf(aA.z); s0 = fmaf(d, d, s0);
            d = pA.w - __logf(aA.w); s0 = fmaf(d, d, s0);
            d = pB.x - __logf(aB.x); s1 = fmaf(d, d, s1);
            d = pB.y - __logf(aB.y); s1 = fmaf(d, d, s1);
            d = pB.z - __logf(aB.z); s1 = fmaf(d, d, s1);
            d = pB.w - __logf(aB.w); s1 = fmaf(d, d, s1);
            d = pC.x - __logf(aC.x); s2 = fmaf(d, d, s2);
            d = pC.y - __logf(aC.y); s2 = fmaf(d, d, s2);
            d = pC.z - __logf(aC.z); s2 = fmaf(d, d, s2);
            d = pC.w - __logf(aC.w); s2 = fmaf(d, d, s2);
            d = pD.x - __logf(aD.x); s3 = fmaf(d, d, s3);
            d = pD.y - __logf(aD.y); s3 = fmaf(d, d, s3);
            d = pD.z - __logf(aD.z); s3 = fmaf(d, d, s3);
            d = pD.w - __logf(aD.w); s3 = fmaf(d, d, s3);
        }
        // Remaining full chunks.
        for (; c < nfull; c += 32) {
            float4 p = p4[c];
            float4 a = a4[c];
            float d;
            d = p.x - __logf(a.x); s0 = fmaf(d, d, s0);
            d = p.y - __logf(a.y); s1 = fmaf(d, d, s1);
            d = p.z - __logf(a.z); s2 = fmaf(d, d, s2);
            d = p.w - __logf(a.w); s3 = fmaf(d, d, s3);
        }
        // Partial tail chunk (1..3 valid elems); owned by one lane.
        // Safe read: L&3 != 0 implies L < T, so chunk nfull < C.
        if ((L & 3) && lane == (nfull & 31)) {
            float4 p = p4[nfull];
            float4 a = a4[nfull];
            int rem = L & 3;
            float d;
            d = p.x - __logf(a.x); s0 = fmaf(d, d, s0);
            if (rem > 1) { d = p.y - __logf(a.y); s1 = fmaf(d, d, s1); }
            if (rem > 2) { d = p.z - __logf(a.z); s2 = fmaf(d, d, s2); }
        }

        float s = (s0 + s1) + (s2 + s3);
        // Warp reduction (fixed order -> deterministic).
        #pragma unroll
        for (int off = 16; off > 0; off >>= 1)
            s += __shfl_down_sync(0xFFFFFFFFu, s, off);
        if (lane == 0)
            g_row_mse[row] = s * __frcp_rn((float)L);
    }

    // Completion signal; last CTA reduces all rows in fixed order.
    __syncthreads();
    __shared__ bool s_is_last;
    if (threadIdx.x == 0) {
        __threadfence();
        int old = atomicAdd(&g_done_ctr, 1);
        s_is_last = (old == (int)gridDim.x - 1);
    }
    __syncthreads();

    if (s_is_last) {
        float v = 0.0f;
        for (int i = threadIdx.x; i < B; i += BLOCK)   // fixed strided order
            v += g_row_mse[i];
        __shared__ float warp_sums[BLOCK / 32];
        #pragma unroll
        for (int off = 16; off > 0; off >>= 1)
            v += __shfl_down_sync(0xFFFFFFFFu, v, off);
        if ((threadIdx.x & 31) == 0)
            warp_sums[threadIdx.x >> 5] = v;
        __syncthreads();
        if (threadIdx.x == 0) {
            float t = 0.0f;
            #pragma unroll
            for (int w = 0; w < BLOCK / 32; w++)
                t += warp_sums[w];
            out[0] = t / (float)B;
            g_done_ctr = 0;   // reset for next graph replay
        }
    }
}

extern "C" void kernel_launch(void* const* d_in, const int* in_sizes, int n_in,
                              void* d_out, int out_size) {
    const float* pred  = (const float*)d_in[0];
    const float* align = (const float*)d_in[1];
    const int*   lens  = (const int*)d_in[2];
    float* out = (float*)d_out;

    const int B = in_sizes[2];
    const int T = in_sizes[0] / B;
    const int C = T >> 2;

    constexpr int BLOCK = 128;                     // 4 warps per CTA
    int grid = (B + (BLOCK / 32) - 1) / (BLOCK / 32);  // one warp per row
    if (grid < 1) grid = 1;
    if (grid > 4096) grid = 4096;

    dploss_warprow_kernel<BLOCK><<<grid, BLOCK>>>(pred, align, lens, out, C, B);
}